// round 16
// baseline (speedup 1.0000x reference)
#include <cuda_runtime.h>
#include <cuda_fp16.h>
#include <cstdint>
#include <math.h>

#define BATCH 2048
#define NMOL 16
#define CA 512
#define NROWS (BATCH * NMOL)   // 32768
#define NCH 37                 // 5 chunks (GEMM1, k=80) + 32 chunks (GEMM2, k=512)
#define NTILES 1536            // 512 row-tiles x 3 branches (branch-major)

// fp16 scratch for K, Q, V (96 MB) + prepped fp16 weight stages
__device__ __half g_scratch_h[3ULL * NROWS * CA];
// per (branch, chunk): 16 warp-slices x 1024 B, each slice [n_local][t4][e]
__device__ uint4 g_wstage[3 * NCH * 1024];   // 16 KB per stage

// ---------------------------------------------------------------------------
__device__ __forceinline__ uint32_t smem_u32(const void* p) {
    uint32_t a;
    asm("{ .reg .u64 t; cvta.to.shared.u64 t, %1; cvt.u32.u64 %0, t; }" : "=r"(a) : "l"(p));
    return a;
}
__device__ __forceinline__ void cpa16(uint32_t dst, const void* src) {
    asm volatile("cp.async.cg.shared.global [%0], [%1], 16;" :: "r"(dst), "l"(src));
}
#define CPA_COMMIT() asm volatile("cp.async.commit_group;" ::: "memory")
#define CPA_WAIT1()  asm volatile("cp.async.wait_group 1;" ::: "memory")
#define CPA_WAIT0()  asm volatile("cp.async.wait_group 0;" ::: "memory")

__device__ __forceinline__ void mma_f16(float d[4], const unsigned a[4], const unsigned b[2]) {
    asm volatile(
        "mma.sync.aligned.m16n8k16.row.col.f32.f16.f16.f32 "
        "{%0,%1,%2,%3}, {%4,%5,%6,%7}, {%8,%9}, {%0,%1,%2,%3};\n"
        : "+f"(d[0]), "+f"(d[1]), "+f"(d[2]), "+f"(d[3])
        : "r"(a[0]), "r"(a[1]), "r"(a[2]), "r"(a[3]),
          "r"(b[0]), "r"(b[1]));
}

__device__ __forceinline__ void ldmx4(unsigned& r0, unsigned& r1, unsigned& r2,
                                      unsigned& r3, uint32_t addr) {
    asm volatile("ldmatrix.sync.aligned.m8n8.x4.shared.b16 {%0,%1,%2,%3}, [%4];"
        : "=r"(r0), "=r"(r1), "=r"(r2), "=r"(r3) : "r"(addr));
}
__device__ __forceinline__ void ldmx4t(unsigned& r0, unsigned& r1, unsigned& r2,
                                       unsigned& r3, uint32_t addr) {
    asm volatile("ldmatrix.sync.aligned.m8n8.x4.trans.shared.b16 {%0,%1,%2,%3}, [%4];"
        : "=r"(r0), "=r"(r1), "=r"(r2), "=r"(r3) : "r"(addr));
}

__device__ __forceinline__ unsigned h2u(__half2 h) {
    return *reinterpret_cast<unsigned*>(&h);
}

// pair-interleave within a 16-group: k -> ((k&6)<<1) + ((k>>3)<<1) + (k&1)
__device__ __forceinline__ int p16(int k) {
    return ((k & 6) << 1) + (((k >> 3) & 1) << 1) + (k & 1);
}

// ---------------------------------------------------------------------------
// Prologue: weights -> fp16 per-warp slice blobs (4 blocks/stage, grid 444).
// halves index within a stage: (n>>5)*512 + (n&31)*16 + t4*4 + e
// ---------------------------------------------------------------------------
__global__ void __launch_bounds__(1024)
prep_weights(const float* __restrict__ Wkh, const float* __restrict__ Wko,
             const float* __restrict__ Wqh, const float* __restrict__ Wqo,
             const float* __restrict__ Wvh, const float* __restrict__ Wvo)
{
    const int sg   = blockIdx.x >> 2;
    const int quar = blockIdx.x & 3;
    const int br = sg / NCH;
    const int s  = sg % NCH;
    const float* Wh = (br == 0) ? Wkh : (br == 1 ? Wqh : Wvh);
    const float* Wo = (br == 0) ? Wko : (br == 1 ? Wqo : Wvo);

    const float* W; int kbase, Krows;
    if (s < 5) { W = Wh; kbase = s * 16;       Krows = 70;  }
    else       { W = Wo; kbase = (s - 5) * 16; Krows = 512; }

    unsigned short* dst = (unsigned short*)&g_wstage[((size_t)br * NCH + s) * 1024];
    const int lo = quar * 2048;
    for (int idx = lo + threadIdx.x; idx < lo + 2048; idx += 1024) {
        int kl = idx >> 9;        // 0..15
        int n  = idx & 511;
        int kg = kbase + kl;
        float v = (kg < Krows) ? W[(size_t)kg * 512 + n] : 0.f;
        int t4 = (kl & 7) >> 1;
        int e  = ((kl >> 3) << 1) | (kl & 1);
        dst[(n >> 5) * 512 + (n & 31) * 16 + t4 * 4 + e] = __half_as_ushort(__float2half_rn(v));
    }
}

// ---------------------------------------------------------------------------
// Fused fp16 MLP (R12 body) made PERSISTENT: grid = SM count, each CTA
// grid-strides over 1536 tiles (branch-major: by = t/512, bx = t%512).
// smem bytes: XE [0, 10240) | H [10240, 77824) | rings [77824, 126976)
// ---------------------------------------------------------------------------
#define XE_OFF    0
#define H_OFF     10240
#define STAGE_OFF 77824
#define SMEM_BYTES (STAGE_OFF + 16 * 3072)   // 126976

__global__ void __launch_bounds__(512, 1)
mlp_kernel(const float* __restrict__ x, const float* __restrict__ pos,
           const float* __restrict__ bkh, const float* __restrict__ bko,
           const float* __restrict__ bqh, const float* __restrict__ bqo,
           const float* __restrict__ bvh, const float* __restrict__ bvo)
{
    extern __shared__ char smem[];
    const uint32_t smem_base = smem_u32(smem);
    const int tid  = threadIdx.x;
    const int G    = gridDim.x;

    const int lane = tid & 31;
    const int warp = tid >> 5;       // 16 warps, each owns 32 N cols
    const int g  = lane >> 2;
    const int t4 = lane & 3;
    const int nw = warp * 32;

    const uint32_t ringb = smem_base + STAGE_OFF + warp * 3072;
    const __half*  ringh = (const __half*)(smem + STAGE_OFF) + warp * 1536;
    const int lob = g * 16 + t4 * 4;  // lane offset into a B buffer (halves)

    for (int t = blockIdx.x; t < NTILES; t += G) {
        const int by   = t >> 9;          // branch
        const int row0 = (t & 511) * 64;

        const float* bh = (by == 0) ? bkh : (by == 1 ? bqh : bvh);
        const float* bo = (by == 0) ? bko : (by == 1 ? bqo : bvo);
        __half* outh = g_scratch_h + (size_t)by * NROWS * CA;

        const char* wsrc = (const char*)(g_wstage + (size_t)by * NCH * 1024)
                           + warp * 1024 + lane * 16;
        uint32_t wb = ringb;
        const __half* bp = ringh;

        // prologue: stage chunks 0, 1
        cpa16(wb + lane * 16, wsrc); cpa16(wb + lane * 16 + 512, wsrc + 512);
        CPA_COMMIT(); wsrc += 16384; wb += 1024;
        cpa16(wb + lane * 16, wsrc); cpa16(wb + lane * 16 + 512, wsrc + 512);
        CPA_COMMIT(); wsrc += 16384; wb += 1024;

        // ---- build XE (fp16, pair-interleaved k order) ----
        // safe vs stragglers of previous tile: they only touch H/ring there.
        {
            __half* XE = (__half*)(smem + XE_OFF);
            for (int idx = tid; idx < 64 * 80; idx += 512) {
                int r = idx / 80, c = idx - r * 80;
                int rg = row0 + r;
                float v = 0.f;
                if (c < 64)      v = x[(size_t)rg * 64 + c];
                else if (c < 70) v = pos[(rg & 15) * 6 + (c - 64)];
                XE[r * 80 + (c >> 4) * 16 + p16(c & 15)] = __float2half_rn(v);
            }
        }

        float acc[4][4][4];
        #pragma unroll
        for (int i = 0; i < 4; i++)
            #pragma unroll
            for (int j = 0; j < 4; j++)
                #pragma unroll
                for (int q = 0; q < 4; q++) acc[i][j][q] = 0.f;

        __syncthreads();   // XE visible to all warps (also fences prev tile)

        auto issue = [&]() {
            cpa16(wb + lane * 16, wsrc);
            cpa16(wb + lane * 16 + 512, wsrc + 512);
            CPA_COMMIT();
            wsrc += 16384;
            wb = (wb == ringb + 2048) ? ringb : wb + 1024;
        };
        auto load_b = [&](unsigned bf[4][2]) {
            const __half* bq = bp + lob;
            #pragma unroll
            for (int nt = 0; nt < 4; nt++) {
                uint2 b = *(const uint2*)(bq + nt * 128);
                bf[nt][0] = b.x; bf[nt][1] = b.y;
            }
            bp = (bp == ringh + 1024) ? ringh : bp + 512;
        };

        // ================= GEMM1: 5 chunks, A stride 80 =================
        {
            const __half* ap = (const __half*)(smem + XE_OFF) + g * 80 + t4 * 4;
            #pragma unroll 1
            for (int s = 0; s < 5; ++s) {
                CPA_WAIT1();
                issue();                              // chunk s+2 (2..6)
                unsigned bf[4][2];
                load_b(bf);
                #pragma unroll
                for (int mt = 0; mt < 4; mt++) {
                    unsigned af[4];
                    uint2 lo = *(const uint2*)(ap + mt * 1280);
                    uint2 hi = *(const uint2*)(ap + mt * 1280 + 640);
                    af[0] = lo.x; af[2] = lo.y;
                    af[1] = hi.x; af[3] = hi.y;
                    #pragma unroll
                    for (int nt = 0; nt < 4; nt++)
                        mma_f16(acc[mt][nt], af, bf[nt]);
                }
                ap += 16;
            }
        }

        // ---- epilogue1: H = silu(D1 + bh), fp16 pair-interleaved ----
        {
            __half* H = (__half*)(smem + H_OFF);
            #pragma unroll
            for (int mt = 0; mt < 4; mt++) {
                #pragma unroll
                for (int nt = 0; nt < 4; nt++) {
                    int col = nw + nt * 8 + 2 * t4;
                    int r0  = mt * 16 + g;
                    float b0 = bh[col], b1 = bh[col + 1];
                    int cl = col & 15;
                    int pp = ((cl & 6) << 1) + ((cl >> 3) << 1);
                    int off = r0 * 528 + (col >> 4) * 16 + pp;
                    float h0 = acc[mt][nt][0] + b0; h0 = h0 / (1.f + __expf(-h0));
                    float h1 = acc[mt][nt][1] + b1; h1 = h1 / (1.f + __expf(-h1));
                    float h2 = acc[mt][nt][2] + b0; h2 = h2 / (1.f + __expf(-h2));
                    float h3 = acc[mt][nt][3] + b1; h3 = h3 / (1.f + __expf(-h3));
                    *(__half2*)(H + off)            = __floats2half2_rn(h0, h1);
                    *(__half2*)(H + off + 8 * 528)  = __floats2half2_rn(h2, h3);
                    acc[mt][nt][0] = 0.f; acc[mt][nt][1] = 0.f;
                    acc[mt][nt][2] = 0.f; acc[mt][nt][3] = 0.f;
                }
            }
            __syncthreads();   // H visible to all warps
        }

        // ================= GEMM2: 32 chunks, A stride 528 =================
        {
            const __half* ap = (const __half*)(smem + H_OFF) + g * 528 + t4 * 4;

            // chunks 5..34 (wait 1, issue s+2 = 7..36)
            #pragma unroll 1
            for (int it = 0; it < 30; ++it) {
                CPA_WAIT1();
                issue();
                unsigned bf[4][2];
                load_b(bf);
                #pragma unroll
                for (int mt = 0; mt < 4; mt++) {
                    unsigned af[4];
                    uint2 lo = *(const uint2*)(ap + mt * 8448);
                    uint2 hi = *(const uint2*)(ap + mt * 8448 + 4224);
                    af[0] = lo.x; af[2] = lo.y;
                    af[1] = hi.x; af[3] = hi.y;
                    #pragma unroll
                    for (int nt = 0; nt < 4; nt++)
                        mma_f16(acc[mt][nt], af, bf[nt]);
                }
                ap += 16;
            }

            // peeled chunk 35: wait 1, no issue
            {
                CPA_WAIT1();
                unsigned bf[4][2];
                load_b(bf);
                #pragma unroll
                for (int mt = 0; mt < 4; mt++) {
                    unsigned af[4];
                    uint2 lo = *(const uint2*)(ap + mt * 8448);
                    uint2 hi = *(const uint2*)(ap + mt * 8448 + 4224);
                    af[0] = lo.x; af[2] = lo.y;
                    af[1] = hi.x; af[3] = hi.y;
                    #pragma unroll
                    for (int nt = 0; nt < 4; nt++)
                        mma_f16(acc[mt][nt], af, bf[nt]);
                }
                ap += 16;
            }

            // peeled chunk 36: wait 0 (ring fully drained for next tile)
            {
                CPA_WAIT0();
                unsigned bf[4][2];
                load_b(bf);
                #pragma unroll
                for (int mt = 0; mt < 4; mt++) {
                    unsigned af[4];
                    uint2 lo = *(const uint2*)(ap + mt * 8448);
                    uint2 hi = *(const uint2*)(ap + mt * 8448 + 4224);
                    af[0] = lo.x; af[2] = lo.y;
                    af[1] = hi.x; af[3] = hi.y;
                    #pragma unroll
                    for (int nt = 0; nt < 4; nt++)
                        mma_f16(acc[mt][nt], af, bf[nt]);
                }
            }
        }

        // ---- epilogue2: scratch(fp16) = D2 + bo ----
        #pragma unroll
        for (int mt = 0; mt < 4; mt++) {
            #pragma unroll
            for (int nt = 0; nt < 4; nt++) {
                int col = nw + nt * 8 + 2 * t4;
                int r0  = mt * 16 + g;
                float b0 = bo[col], b1 = bo[col + 1];
                *(__half2*)(outh + (size_t)(row0 + r0) * 512 + col)
                    = __floats2half2_rn(acc[mt][nt][0] + b0, acc[mt][nt][1] + b1);
                *(__half2*)(outh + (size_t)(row0 + r0 + 8) * 512 + col)
                    = __floats2half2_rn(acc[mt][nt][2] + b0, acc[mt][nt][3] + b1);
            }
        }
    }
}

// ---------------------------------------------------------------------------
// Attention v2: row-major smem (stride 520 halves) + ldmatrix fragments.
// ---------------------------------------------------------------------------
#define KS_B 0
#define QS_B 16640
#define VS_B 33280
#define ATTN_SMEM_BYTES 49920

__global__ void __launch_bounds__(256)
attn_kernel(const float* __restrict__ fm, float* __restrict__ out)
{
    extern __shared__ char smem[];
    float* fbuf = (float*)smem;
    const uint32_t sb = smem_u32(smem);

    const int b    = blockIdx.x;
    const int tid  = threadIdx.x;
    const int warp = tid >> 5;       // head c
    const int lane = tid & 31;
    const int g    = lane >> 2;
    const int t4   = lane & 3;

    const uint4* kg = (const uint4*)g_scratch_h + (size_t)b * 1024;
    const uint4* qg = kg + 2097152;   // NROWS*CA/8
    const uint4* vg = kg + 4194304;

    #pragma unroll
    for (int it = 0; it < 4; it++) {
        int f = tid + it * 256;                      // uint4 index 0..1023
        uint32_t d = (uint32_t)(f >> 6) * 1040 + (uint32_t)(f & 63) * 16;
        *(uint4*)(smem + KS_B + d) = kg[f];
        *(uint4*)(smem + QS_B + d) = qg[f];
        *(uint4*)(smem + VS_B + d) = vg[f];
    }
    __syncthreads();

    const uint32_t ka = sb + KS_B + (uint32_t)(lane & 15) * 1040 + warp * 128
                        + ((lane >> 4) << 4);
    const uint32_t qrow = ((lane & 16) ? 8u : 0u) + (lane & 7);
    const uint32_t qa = sb + QS_B + qrow * 1040 + warp * 128
                        + ((lane & 8) ? 16u : 0u);

    float d0[4] = {0.f, 0.f, 0.f, 0.f};   // j 0..7
    float d1[4] = {0.f, 0.f, 0.f, 0.f};   // j 8..15
    #pragma unroll
    for (int kc = 0; kc < 4; kc++) {
        unsigned a0, a1, a2, a3, q0, q1, q2, q3;
        ldmx4(a0, a1, a2, a3, ka + kc * 32);
        ldmx4(q0, q1, q2, q3, qa + kc * 32);
        unsigned af[4] = {a0, a1, a2, a3};
        unsigned bq0[2] = {q0, q1};
        unsigned bq1[2] = {q2, q3};
        mma_f16(d0, af, bq0);
        mma_f16(d1, af, bq1);
    }

    const float fr0 = __ldg(&fm[g]);
    const float fr1 = __ldg(&fm[g + 8]);
    float w0[4], w1[4];
    #pragma unroll
    for (int e = 0; e < 4; e++) {
        int row = (e >= 2) ? (g + 8) : g;
        float frow = (e >= 2) ? fr1 : fr0;
        int j0 = 2 * t4 + (e & 1);
        int j1 = j0 + 8;
        float fj0 = __ldg(&fm[j0]);
        float fj1 = __ldg(&fm[j1]);
        float a0 = d0[e] * 0.125f * frow * fj0;
        float a1 = d1[e] * 0.125f * frow * fj1;
        float s0 = (a0 > 20.f) ? a0 : log1pf(__expf(a0));
        float s1 = (a1 > 20.f) ? a1 : log1pf(__expf(a1));
        w0[e] = (row == j0) ? 0.f : (s0 + 1e-5f);
        w1[e] = (row == j1) ? 0.f : (s1 + 1e-5f);
    }
    float s0 = w0[0] + w0[1] + w1[0] + w1[1];
    float s1 = w0[2] + w0[3] + w1[2] + w1[3];
    s0 += __shfl_xor_sync(0xffffffffu, s0, 1);
    s0 += __shfl_xor_sync(0xffffffffu, s0, 2);
    s1 += __shfl_xor_sync(0xffffffffu, s1, 1);
    s1 += __shfl_xor_sync(0xffffffffu, s1, 2);
    float i0 = 1.f / s0, i1 = 1.f / s1;
    #pragma unroll
    for (int e = 0; e < 4; e++) {
        int j0 = 2 * t4 + (e & 1);
        float inv = (e >= 2) ? i1 : i0;
        w0[e] = w0[e] * inv * __ldg(&fm[j0]);
        w1[e] = w1[e] * inv * __ldg(&fm[j0 + 8]);
    }

    unsigned aw[4];
    aw[0] = h2u(__floats2half2_rn(w0[0], w0[1]));
    aw[1] = h2u(__floats2half2_rn(w0[2], w0[3]));
    aw[2] = h2u(__floats2half2_rn(w1[0], w1[1]));
    aw[3] = h2u(__floats2half2_rn(w1[2], w1[3]));

    const uint32_t vrow = ((lane & 8) ? 8u : 0u) + (lane & 7);
    const uint32_t va = sb + VS_B + vrow * 1040 + warp * 128
                        + ((lane & 16) ? 16u : 0u);
    float o[8][4];
    #pragma unroll
    for (int np = 0; np < 4; np++) {
        unsigned v0, v1, v2, v3;
        ldmx4t(v0, v1, v2, v3, va + np * 32);
        unsigned bb0[2] = {v0, v1};
        unsigned bb1[2] = {v2, v3};
        o[2*np][0] = o[2*np][1] = o[2*np][2] = o[2*np][3] = 0.f;
        o[2*np+1][0] = o[2*np+1][1] = o[2*np+1][2] = o[2*np+1][3] = 0.f;
        mma_f16(o[2*np],     aw, bb0);
        mma_f16(o[2*np + 1], aw, bb1);
    }

    __syncthreads();
    #pragma unroll
    for (int nt = 0; nt < 8; nt++) {
        float* p0 = fbuf + warp * 1088 + g * 68 + nt * 8 + 2 * t4;
        *(float2*)p0            = make_float2(o[nt][0], o[nt][1]);
        *(float2*)(p0 + 8 * 68) = make_float2(o[nt][2], o[nt][3]);
    }
    __syncthreads();

    {
        int i  = tid >> 4;
        int dq = (tid & 15) * 4;
        float4 acc = make_float4(0.f, 0.f, 0.f, 0.f);
        #pragma unroll
        for (int c = 0; c < 8; c++) {
            float4 v = *(const float4*)(fbuf + c * 1088 + i * 68 + dq);
            acc.x += v.x; acc.y += v.y; acc.z += v.z; acc.w += v.w;
        }
        *(float4*)(out + (size_t)b * 1024 + i * 64 + dq) = acc;
    }
}

// ---------------------------------------------------------------------------
extern "C" void kernel_launch(void* const* d_in, const int* in_sizes, int n_in,
                              void* d_out, int out_size) {
    const float* x   = (const float*)d_in[0];
    const float* fm  = (const float*)d_in[1];
    const float* Wkh = (const float*)d_in[2];
    const float* bkh = (const float*)d_in[3];
    const float* Wko = (const float*)d_in[4];
    const float* bko = (const float*)d_in[5];
    const float* Wqh = (const float*)d_in[6];
    const float* bqh = (const float*)d_in[7];
    const float* Wqo = (const float*)d_in[8];
    const float* bqo = (const float*)d_in[9];
    const float* Wvh = (const float*)d_in[10];
    const float* bvh = (const float*)d_in[11];
    const float* Wvo = (const float*)d_in[12];
    const float* bvo = (const float*)d_in[13];
    const float* pos = (const float*)d_in[14];
    float* out = (float*)d_out;

    cudaFuncSetAttribute(mlp_kernel, cudaFuncAttributeMaxDynamicSharedMemorySize,
                         SMEM_BYTES);
    cudaFuncSetAttribute(attn_kernel, cudaFuncAttributeMaxDynamicSharedMemorySize,
                         ATTN_SMEM_BYTES);

    int nsm = 148;
    cudaDeviceGetAttribute(&nsm, cudaDevAttrMultiProcessorCount, 0);
    if (nsm <= 0 || nsm > NTILES) nsm = 148;

    prep_weights<<<4 * 3 * NCH, 1024>>>(Wkh, Wko, Wqh, Wqo, Wvh, Wvo);

    mlp_kernel<<<nsm, 512, SMEM_BYTES>>>(x, pos, bkh, bko, bqh, bqo, bvh, bvo);

    attn_kernel<<<BATCH, 256, ATTN_SMEM_BYTES>>>(fm, out);
}

// round 17
// speedup vs baseline: 1.0511x; 1.0511x over previous
#include <cuda_runtime.h>
#include <cuda_fp16.h>
#include <cstdint>
#include <math.h>

#define BATCH 2048
#define NMOL 16
#define CA 512
#define NROWS (BATCH * NMOL)   // 32768
#define NCH 37                 // 5 chunks (GEMM1, k=80) + 32 chunks (GEMM2, k=512)

// fp16 scratch for K, Q, V (96 MB) + prepped fp16 weight stages
__device__ __half g_scratch_h[3ULL * NROWS * CA];
// per (branch, chunk): 16 warp-slices x 1024 B, each slice [n_local][t4][e]
__device__ uint4 g_wstage[3 * NCH * 1024];   // 16 KB per stage

// ---------------------------------------------------------------------------
__device__ __forceinline__ uint32_t smem_u32(const void* p) {
    uint32_t a;
    asm("{ .reg .u64 t; cvta.to.shared.u64 t, %1; cvt.u32.u64 %0, t; }" : "=r"(a) : "l"(p));
    return a;
}
__device__ __forceinline__ void cpa16(uint32_t dst, const void* src) {
    asm volatile("cp.async.cg.shared.global [%0], [%1], 16;" :: "r"(dst), "l"(src));
}
#define CPA_COMMIT() asm volatile("cp.async.commit_group;" ::: "memory")
#define CPA_WAIT1()  asm volatile("cp.async.wait_group 1;" ::: "memory")
#define CPA_WAIT0()  asm volatile("cp.async.wait_group 0;" ::: "memory")

__device__ __forceinline__ void mma_f16(float d[4], const unsigned a[4], const unsigned b[2]) {
    asm volatile(
        "mma.sync.aligned.m16n8k16.row.col.f32.f16.f16.f32 "
        "{%0,%1,%2,%3}, {%4,%5,%6,%7}, {%8,%9}, {%0,%1,%2,%3};\n"
        : "+f"(d[0]), "+f"(d[1]), "+f"(d[2]), "+f"(d[3])
        : "r"(a[0]), "r"(a[1]), "r"(a[2]), "r"(a[3]),
          "r"(b[0]), "r"(b[1]));
}

__device__ __forceinline__ void ldmx4(unsigned& r0, unsigned& r1, unsigned& r2,
                                      unsigned& r3, uint32_t addr) {
    asm volatile("ldmatrix.sync.aligned.m8n8.x4.shared.b16 {%0,%1,%2,%3}, [%4];"
        : "=r"(r0), "=r"(r1), "=r"(r2), "=r"(r3) : "r"(addr));
}
__device__ __forceinline__ void ldmx4t(unsigned& r0, unsigned& r1, unsigned& r2,
                                       unsigned& r3, uint32_t addr) {
    asm volatile("ldmatrix.sync.aligned.m8n8.x4.trans.shared.b16 {%0,%1,%2,%3}, [%4];"
        : "=r"(r0), "=r"(r1), "=r"(r2), "=r"(r3) : "r"(addr));
}

__device__ __forceinline__ unsigned h2u(__half2 h) {
    return *reinterpret_cast<unsigned*>(&h);
}

// pair-interleave within a 16-group: k -> ((k&6)<<1) + ((k>>3)<<1) + (k&1)
__device__ __forceinline__ int p16(int k) {
    return ((k & 6) << 1) + (((k >> 3) & 1) << 1) + (k & 1);
}

// ---------------------------------------------------------------------------
// Prologue: weights -> fp16 per-warp slice blobs (4 blocks/stage, grid 444).
// halves index within a stage: (n>>5)*512 + (n&31)*16 + t4*4 + e
// ---------------------------------------------------------------------------
__global__ void __launch_bounds__(1024)
prep_weights(const float* __restrict__ Wkh, const float* __restrict__ Wko,
             const float* __restrict__ Wqh, const float* __restrict__ Wqo,
             const float* __restrict__ Wvh, const float* __restrict__ Wvo)
{
    const int sg   = blockIdx.x >> 2;
    const int quar = blockIdx.x & 3;
    const int br = sg / NCH;
    const int s  = sg % NCH;
    const float* Wh = (br == 0) ? Wkh : (br == 1 ? Wqh : Wvh);
    const float* Wo = (br == 0) ? Wko : (br == 1 ? Wqo : Wvo);

    const float* W; int kbase, Krows;
    if (s < 5) { W = Wh; kbase = s * 16;       Krows = 70;  }
    else       { W = Wo; kbase = (s - 5) * 16; Krows = 512; }

    unsigned short* dst = (unsigned short*)&g_wstage[((size_t)br * NCH + s) * 1024];
    const int lo = quar * 2048;
    for (int idx = lo + threadIdx.x; idx < lo + 2048; idx += 1024) {
        int kl = idx >> 9;        // 0..15
        int n  = idx & 511;
        int kg = kbase + kl;
        float v = (kg < Krows) ? W[(size_t)kg * 512 + n] : 0.f;
        int t4 = (kl & 7) >> 1;
        int e  = ((kl >> 3) << 1) | (kl & 1);
        dst[(n >> 5) * 512 + (n & 31) * 16 + t4 * 4 + e] = __half_as_ushort(__float2half_rn(v));
    }
}

// ---------------------------------------------------------------------------
// Fused fp16 MLP (R12 exact): warp-private staging, 3-deep ring,
// fully strength-reduced specialized loops.
// smem bytes: XE [0, 10240) | H [10240, 77824) | rings [77824, 126976)
// ---------------------------------------------------------------------------
#define XE_OFF    0
#define H_OFF     10240
#define STAGE_OFF 77824
#define SMEM_BYTES (STAGE_OFF + 16 * 3072)   // 126976

__global__ void __launch_bounds__(512, 1)
mlp_kernel(const float* __restrict__ x, const float* __restrict__ pos,
           const float* __restrict__ bkh, const float* __restrict__ bko,
           const float* __restrict__ bqh, const float* __restrict__ bqo,
           const float* __restrict__ bvh, const float* __restrict__ bvo)
{
    extern __shared__ char smem[];
    const uint32_t smem_base = smem_u32(smem);
    const int tid  = threadIdx.x;
    const int by   = blockIdx.y;
    const int row0 = blockIdx.x * 64;

    const float* bh = (by == 0) ? bkh : (by == 1 ? bqh : bvh);
    const float* bo = (by == 0) ? bko : (by == 1 ? bqo : bvo);
    __half* outh = g_scratch_h + (size_t)by * NROWS * CA;

    const int lane = tid & 31;
    const int warp = tid >> 5;       // 16 warps, each owns 32 N cols
    const int g  = lane >> 2;
    const int t4 = lane & 3;
    const int nw = warp * 32;

    // running weight-source pointer (advances 16 KB per chunk)
    const char* wsrc = (const char*)(g_wstage + (size_t)by * NCH * 1024)
                       + warp * 1024 + lane * 16;

    // smem ring: 3 x 1024 B per warp
    const uint32_t ringb = smem_base + STAGE_OFF + warp * 3072;
    const __half*  ringh = (const __half*)(smem + STAGE_OFF) + warp * 1536;

    uint32_t wb = ringb;              // next write buffer (chunk 0 -> buf 0)
    const __half* bp = ringh;         // read buffer for chunk 0
    const int lob = g * 16 + t4 * 4;  // lane offset into a B buffer (halves)

    // prologue: stage chunks 0, 1
    cpa16(wb + lane * 16, wsrc); cpa16(wb + lane * 16 + 512, wsrc + 512);
    CPA_COMMIT(); wsrc += 16384; wb += 1024;
    cpa16(wb + lane * 16, wsrc); cpa16(wb + lane * 16 + 512, wsrc + 512);
    CPA_COMMIT(); wsrc += 16384; wb += 1024;

    // ---- build XE (fp16, pair-interleaved k order) ----
    {
        __half* XE = (__half*)(smem + XE_OFF);
        for (int idx = tid; idx < 64 * 80; idx += 512) {
            int r = idx / 80, c = idx - r * 80;
            int rg = row0 + r;
            float v = 0.f;
            if (c < 64)      v = x[(size_t)rg * 64 + c];
            else if (c < 70) v = pos[(rg & 15) * 6 + (c - 64)];
            XE[r * 80 + (c >> 4) * 16 + p16(c & 15)] = __float2half_rn(v);
        }
    }

    float acc[4][4][4];
    #pragma unroll
    for (int i = 0; i < 4; i++)
        #pragma unroll
        for (int j = 0; j < 4; j++)
            #pragma unroll
            for (int q = 0; q < 4; q++) acc[i][j][q] = 0.f;

    __syncthreads();   // XE visible to all warps

    auto issue = [&]() {
        cpa16(wb + lane * 16, wsrc);
        cpa16(wb + lane * 16 + 512, wsrc + 512);
        CPA_COMMIT();
        wsrc += 16384;
        wb = (wb == ringb + 2048) ? ringb : wb + 1024;
    };
    auto load_b = [&](unsigned bf[4][2]) {
        const __half* bq = bp + lob;
        #pragma unroll
        for (int nt = 0; nt < 4; nt++) {
            uint2 b = *(const uint2*)(bq + nt * 128);
            bf[nt][0] = b.x; bf[nt][1] = b.y;
        }
        bp = (bp == ringh + 1024) ? ringh : bp + 512;
    };

    // ================= GEMM1: 5 chunks, A stride 80 =================
    {
        const __half* ap = (const __half*)(smem + XE_OFF) + g * 80 + t4 * 4;
        #pragma unroll 1
        for (int s = 0; s < 5; ++s) {
            CPA_WAIT1();
            issue();                              // chunk s+2 (2..6)
            unsigned bf[4][2];
            load_b(bf);
            #pragma unroll
            for (int mt = 0; mt < 4; mt++) {
                unsigned af[4];
                uint2 lo = *(const uint2*)(ap + mt * 1280);
                uint2 hi = *(const uint2*)(ap + mt * 1280 + 640);
                af[0] = lo.x; af[2] = lo.y;
                af[1] = hi.x; af[3] = hi.y;
                #pragma unroll
                for (int nt = 0; nt < 4; nt++)
                    mma_f16(acc[mt][nt], af, bf[nt]);
            }
            ap += 16;
        }
    }

    // ---- epilogue1: H = silu(D1 + bh), fp16 pair-interleaved ----
    {
        __half* H = (__half*)(smem + H_OFF);
        #pragma unroll
        for (int mt = 0; mt < 4; mt++) {
            #pragma unroll
            for (int nt = 0; nt < 4; nt++) {
                int col = nw + nt * 8 + 2 * t4;
                int r0  = mt * 16 + g;
                float b0 = bh[col], b1 = bh[col + 1];
                int cl = col & 15;
                int pp = ((cl & 6) << 1) + ((cl >> 3) << 1);
                int off = r0 * 528 + (col >> 4) * 16 + pp;
                float h0 = acc[mt][nt][0] + b0; h0 = h0 / (1.f + __expf(-h0));
                float h1 = acc[mt][nt][1] + b1; h1 = h1 / (1.f + __expf(-h1));
                float h2 = acc[mt][nt][2] + b0; h2 = h2 / (1.f + __expf(-h2));
                float h3 = acc[mt][nt][3] + b1; h3 = h3 / (1.f + __expf(-h3));
                *(__half2*)(H + off)            = __floats2half2_rn(h0, h1);
                *(__half2*)(H + off + 8 * 528)  = __floats2half2_rn(h2, h3);
                acc[mt][nt][0] = 0.f; acc[mt][nt][1] = 0.f;
                acc[mt][nt][2] = 0.f; acc[mt][nt][3] = 0.f;
            }
        }
        __syncthreads();   // H visible to all warps
    }

    // ================= GEMM2: 32 chunks, A stride 528 =================
    {
        const __half* ap = (const __half*)(smem + H_OFF) + g * 528 + t4 * 4;

        // main: chunks 5..34 (wait 1, issue s+2 = 7..36)
        #pragma unroll 1
        for (int it = 0; it < 30; ++it) {
            CPA_WAIT1();
            issue();
            unsigned bf[4][2];
            load_b(bf);
            #pragma unroll
            for (int mt = 0; mt < 4; mt++) {
                unsigned af[4];
                uint2 lo = *(const uint2*)(ap + mt * 8448);
                uint2 hi = *(const uint2*)(ap + mt * 8448 + 4224);
                af[0] = lo.x; af[2] = lo.y;
                af[1] = hi.x; af[3] = hi.y;
                #pragma unroll
                for (int nt = 0; nt < 4; nt++)
                    mma_f16(acc[mt][nt], af, bf[nt]);
            }
            ap += 16;
        }

        // peeled chunk 35: wait 1 (35 done, 36 may be in flight), no issue
        {
            CPA_WAIT1();
            unsigned bf[4][2];
            load_b(bf);
            #pragma unroll
            for (int mt = 0; mt < 4; mt++) {
                unsigned af[4];
                uint2 lo = *(const uint2*)(ap + mt * 8448);
                uint2 hi = *(const uint2*)(ap + mt * 8448 + 4224);
                af[0] = lo.x; af[2] = lo.y;
                af[1] = hi.x; af[3] = hi.y;
                #pragma unroll
                for (int nt = 0; nt < 4; nt++)
                    mma_f16(acc[mt][nt], af, bf[nt]);
            }
            ap += 16;
        }

        // peeled chunk 36: wait 0
        {
            CPA_WAIT0();
            unsigned bf[4][2];
            load_b(bf);
            #pragma unroll
            for (int mt = 0; mt < 4; mt++) {
                unsigned af[4];
                uint2 lo = *(const uint2*)(ap + mt * 8448);
                uint2 hi = *(const uint2*)(ap + mt * 8448 + 4224);
                af[0] = lo.x; af[2] = lo.y;
                af[1] = hi.x; af[3] = hi.y;
                #pragma unroll
                for (int nt = 0; nt < 4; nt++)
                    mma_f16(acc[mt][nt], af, bf[nt]);
            }
        }
    }

    // ---- epilogue2: scratch(fp16) = D2 + bo ----
    #pragma unroll
    for (int mt = 0; mt < 4; mt++) {
        #pragma unroll
        for (int nt = 0; nt < 4; nt++) {
            int col = nw + nt * 8 + 2 * t4;
            int r0  = mt * 16 + g;
            float b0 = bo[col], b1 = bo[col + 1];
            *(__half2*)(outh + (size_t)(row0 + r0) * 512 + col)
                = __floats2half2_rn(acc[mt][nt][0] + b0, acc[mt][nt][1] + b1);
            *(__half2*)(outh + (size_t)(row0 + r0 + 8) * 512 + col)
                = __floats2half2_rn(acc[mt][nt][2] + b0, acc[mt][nt][3] + b1);
        }
    }
}

// ---------------------------------------------------------------------------
// Attention v2: row-major smem (stride 520 halves) + ldmatrix fragments.
// ---------------------------------------------------------------------------
#define KS_B 0
#define QS_B 16640
#define VS_B 33280
#define ATTN_SMEM_BYTES 49920

__global__ void __launch_bounds__(256)
attn_kernel(const float* __restrict__ fm, float* __restrict__ out)
{
    extern __shared__ char smem[];
    float* fbuf = (float*)smem;
    const uint32_t sb = smem_u32(smem);

    const int b    = blockIdx.x;
    const int tid  = threadIdx.x;
    const int warp = tid >> 5;       // head c
    const int lane = tid & 31;
    const int g    = lane >> 2;
    const int t4   = lane & 3;

    const uint4* kg = (const uint4*)g_scratch_h + (size_t)b * 1024;
    const uint4* qg = kg + 2097152;   // NROWS*CA/8
    const uint4* vg = kg + 4194304;

    // ---- stage K, Q, V: pure row-major vectorized copy ----
    #pragma unroll
    for (int it = 0; it < 4; it++) {
        int f = tid + it * 256;                      // uint4 index 0..1023
        uint32_t d = (uint32_t)(f >> 6) * 1040 + (uint32_t)(f & 63) * 16;
        *(uint4*)(smem + KS_B + d) = kg[f];
        *(uint4*)(smem + QS_B + d) = qg[f];
        *(uint4*)(smem + VS_B + d) = vg[f];
    }
    __syncthreads();

    const uint32_t ka = sb + KS_B + (uint32_t)(lane & 15) * 1040 + warp * 128
                        + ((lane >> 4) << 4);
    const uint32_t qrow = ((lane & 16) ? 8u : 0u) + (lane & 7);
    const uint32_t qa = sb + QS_B + qrow * 1040 + warp * 128
                        + ((lane & 8) ? 16u : 0u);

    float d0[4] = {0.f, 0.f, 0.f, 0.f};   // j 0..7
    float d1[4] = {0.f, 0.f, 0.f, 0.f};   // j 8..15
    #pragma unroll
    for (int kc = 0; kc < 4; kc++) {
        unsigned a0, a1, a2, a3, q0, q1, q2, q3;
        ldmx4(a0, a1, a2, a3, ka + kc * 32);
        ldmx4(q0, q1, q2, q3, qa + kc * 32);
        unsigned af[4] = {a0, a1, a2, a3};
        unsigned bq0[2] = {q0, q1};
        unsigned bq1[2] = {q2, q3};
        mma_f16(d0, af, bq0);
        mma_f16(d1, af, bq1);
    }

    const float fr0 = __ldg(&fm[g]);
    const float fr1 = __ldg(&fm[g + 8]);
    float w0[4], w1[4];
    #pragma unroll
    for (int e = 0; e < 4; e++) {
        int row = (e >= 2) ? (g + 8) : g;
        float frow = (e >= 2) ? fr1 : fr0;
        int j0 = 2 * t4 + (e & 1);
        int j1 = j0 + 8;
        float fj0 = __ldg(&fm[j0]);
        float fj1 = __ldg(&fm[j1]);
        float a0 = d0[e] * 0.125f * frow * fj0;
        float a1 = d1[e] * 0.125f * frow * fj1;
        float s0 = (a0 > 20.f) ? a0 : log1pf(__expf(a0));
        float s1 = (a1 > 20.f) ? a1 : log1pf(__expf(a1));
        w0[e] = (row == j0) ? 0.f : (s0 + 1e-5f);
        w1[e] = (row == j1) ? 0.f : (s1 + 1e-5f);
    }
    float s0 = w0[0] + w0[1] + w1[0] + w1[1];
    float s1 = w0[2] + w0[3] + w1[2] + w1[3];
    s0 += __shfl_xor_sync(0xffffffffu, s0, 1);
    s0 += __shfl_xor_sync(0xffffffffu, s0, 2);
    s1 += __shfl_xor_sync(0xffffffffu, s1, 1);
    s1 += __shfl_xor_sync(0xffffffffu, s1, 2);
    float i0 = 1.f / s0, i1 = 1.f / s1;
    #pragma unroll
    for (int e = 0; e < 4; e++) {
        int j0 = 2 * t4 + (e & 1);
        float inv = (e >= 2) ? i1 : i0;
        w0[e] = w0[e] * inv * __ldg(&fm[j0]);
        w1[e] = w1[e] * inv * __ldg(&fm[j0 + 8]);
    }

    unsigned aw[4];
    aw[0] = h2u(__floats2half2_rn(w0[0], w0[1]));
    aw[1] = h2u(__floats2half2_rn(w0[2], w0[3]));
    aw[2] = h2u(__floats2half2_rn(w1[0], w1[1]));
    aw[3] = h2u(__floats2half2_rn(w1[2], w1[3]));

    const uint32_t vrow = ((lane & 8) ? 8u : 0u) + (lane & 7);
    const uint32_t va = sb + VS_B + vrow * 1040 + warp * 128
                        + ((lane & 16) ? 16u : 0u);
    float o[8][4];
    #pragma unroll
    for (int np = 0; np < 4; np++) {
        unsigned v0, v1, v2, v3;
        ldmx4t(v0, v1, v2, v3, va + np * 32);
        unsigned bb0[2] = {v0, v1};
        unsigned bb1[2] = {v2, v3};
        o[2*np][0] = o[2*np][1] = o[2*np][2] = o[2*np][3] = 0.f;
        o[2*np+1][0] = o[2*np+1][1] = o[2*np+1][2] = o[2*np+1][3] = 0.f;
        mma_f16(o[2*np],     aw, bb0);
        mma_f16(o[2*np + 1], aw, bb1);
    }

    __syncthreads();
    #pragma unroll
    for (int nt = 0; nt < 8; nt++) {
        float* p0 = fbuf + warp * 1088 + g * 68 + nt * 8 + 2 * t4;
        *(float2*)p0            = make_float2(o[nt][0], o[nt][1]);
        *(float2*)(p0 + 8 * 68) = make_float2(o[nt][2], o[nt][3]);
    }
    __syncthreads();

    {
        int i  = tid >> 4;
        int dq = (tid & 15) * 4;
        float4 acc = make_float4(0.f, 0.f, 0.f, 0.f);
        #pragma unroll
        for (int c = 0; c < 8; c++) {
            float4 v = *(const float4*)(fbuf + c * 1088 + i * 68 + dq);
            acc.x += v.x; acc.y += v.y; acc.z += v.z; acc.w += v.w;
        }
        *(float4*)(out + (size_t)b * 1024 + i * 64 + dq) = acc;
    }
}

// ---------------------------------------------------------------------------
extern "C" void kernel_launch(void* const* d_in, const int* in_sizes, int n_in,
                              void* d_out, int out_size) {
    const float* x   = (const float*)d_in[0];
    const float* fm  = (const float*)d_in[1];
    const float* Wkh = (const float*)d_in[2];
    const float* bkh = (const float*)d_in[3];
    const float* Wko = (const float*)d_in[4];
    const float* bko = (const float*)d_in[5];
    const float* Wqh = (const float*)d_in[6];
    const float* bqh = (const float*)d_in[7];
    const float* Wqo = (const float*)d_in[8];
    const float* bqo = (const float*)d_in[9];
    const float* Wvh = (const float*)d_in[10];
    const float* bvh = (const float*)d_in[11];
    const float* Wvo = (const float*)d_in[12];
    const float* bvo = (const float*)d_in[13];
    const float* pos = (const float*)d_in[14];
    float* out = (float*)d_out;

    cudaFuncSetAttribute(mlp_kernel, cudaFuncAttributeMaxDynamicSharedMemorySize,
                         SMEM_BYTES);
    cudaFuncSetAttribute(attn_kernel, cudaFuncAttributeMaxDynamicSharedMemorySize,
                         ATTN_SMEM_BYTES);

    prep_weights<<<4 * 3 * NCH, 1024>>>(Wkh, Wko, Wqh, Wqo, Wvh, Wvo);

    dim3 grid(NROWS / 64, 3);
    mlp_kernel<<<grid, 512, SMEM_BYTES>>>(x, pos, bkh, bko, bqh, bqo, bvh, bvo);

    attn_kernel<<<BATCH, 256, ATTN_SMEM_BYTES>>>(fm, out);
}